// round 11
// baseline (speedup 1.0000x reference)
#include <cuda_runtime.h>

#define NS 8
#define NC 128
#define KT 32
#define KF 16
#define FREQ 256
#define NFW 15
#define THR 15.0f
#define LPRE 431
#define NPOT 6400
#define MARGIN 0.05f
#define NCAND 16

#define TP 33
#define RP 17
#define RROW_OFF  14224          /* tile = 431*33 = 14223 */
#define S_OFF     21552          /* Rrow = 431*17 = 7327 -> 7328 */
#define X2_OFF    27952          /* variance array (lazy) */
#define RROW2_OFF 34352          /* lazy */
#define XP_OFF    41680          /* xpatch[2][512]; cold path reuses as wbuf */
#define SMEM_F    42704          /* 170,816 bytes */

__device__ unsigned g_poolw[NS * NFW * 4];
__device__ unsigned g_done;

__global__ __launch_bounds__(512, 1)
void spyke_kernel(const float* __restrict__ X, const float* __restrict__ W,
                  int* __restrict__ out)
{
    extern __shared__ float sm[];
    float* tile   = sm;
    float* Rrow   = sm + RROW_OFF;
    float* Sarr   = sm + S_OFF;
    float* Varr   = sm + X2_OFF;
    float* Rrow2  = sm + RROW2_OFF;
    float* xpatch = sm + XP_OFF;

    __shared__ unsigned long long s_cand[NCAND];
    __shared__ int s_p[NCAND];
    __shared__ float s_cw[NC], s_cb[NC];
    __shared__ unsigned s_pool[4], s_res[4];
    __shared__ int s_sig_i, s_rcnt, s_last, s_any, s_key0, s_key1, s_cfired;
    __shared__ int s_rem[NC];

    const int s = blockIdx.x / NFW, fwin = blockIdx.x % NFW;
    const int tid = threadIdx.x, sec = s * 400;
    const int lane = tid & 31, wid = tid >> 5;

    if (tid < NCAND) s_cand[tid] = 0ULL;
    if (tid < 4) { s_pool[tid] = 0u; s_res[tid] = 0u; }
    if (tid == 0) { s_rcnt = 0; s_sig_i = 0; }

    // ---- stage X window: float4 loads ----
    {
        const float4* X4 = (const float4*)X;
        for (int i = tid; i < LPRE * 8; i += 512) {
            int r = i >> 3, c = i & 7;
            float4 v = X4[(sec + r) * 64 + fwin * 4 + c];
            float* dst = tile + r * TP + c * 4;
            dst[0] = v.x; dst[1] = v.y; dst[2] = v.z; dst[3] = v.w;
        }
    }
    __syncthreads();

    // ---- row sliding sums over kf-window of 16 ----
    if (tid < LPRE) {
        float a = 0.f;
        #pragma unroll
        for (int c = 0; c < 16; ++c) a += tile[tid*TP + c];
        Rrow[tid*RP] = a;
        #pragma unroll 5
        for (int f = 1; f < 16; ++f) {
            a += tile[tid*TP + f + 15] - tile[tid*TP + f - 1];
            Rrow[tid*RP + f] = a;
        }
    }
    __syncthreads();

    // ---- column sliding over kt-window of 32: S + per-region argmax ----
    if (tid < 400) {
        int f = tid & 15, t0 = (tid >> 4) * 16;
        float a = 0.f;
        #pragma unroll 8
        for (int k = 0; k < 32; ++k) a += Rrow[(t0+k)*RP+f];
        unsigned long long lkey[2] = {0ULL, 0ULL};
        int reg0 = t0 / 25;
        for (int t = t0; t < t0 + 16; ++t) {
            int p = t*16 + f;
            Sarr[p] = a;
            unsigned long long key =
                ((unsigned long long)__float_as_uint(a) << 13) | (unsigned)p;
            int ri = (t / 25) - reg0;
            if (key > lkey[ri]) lkey[ri] = key;
            if (t <= 398) a += Rrow[(t+32)*RP+f] - Rrow[t*RP+f];
        }
        atomicMax(&s_cand[reg0], lkey[0]);
        if (lkey[1] && reg0 + 1 < NCAND) atomicMax(&s_cand[reg0 + 1], lkey[1]);
    }
    __syncthreads();

    // ---- sort candidates descending ----
    if (tid < NCAND) {
        unsigned long long mykey = s_cand[tid];
        int rank = 0;
        for (int j = 0; j < NCAND; ++j) rank += (s_cand[j] > mykey);
        s_p[rank] = (int)(mykey & 8191ULL);
    }
    __syncthreads();

    const float4* Ws = (const float4*)(W + (size_t)s * NC * 512);
    const int gr = tid >> 4, gc = tid & 15;

    // stage candidate 0 patch
    {
        int p = s_p[0], t = p >> 4, f = p & 15;
        xpatch[tid] = tile[(t + gr) * TP + f + gc];
    }
    __syncthreads();

    // ---- candidate probes: warp-per-channel coalesced matvec ----
    for (int k = 0; k < NCAND; ++k) {
        const float4* xp4 = (const float4*)(xpatch + (k & 1) * 512);
        float4 xq0 = xp4[lane], xq1 = xp4[lane+32], xq2 = xp4[lane+64], xq3 = xp4[lane+96];
        if (k + 1 < NCAND) {
            int p = s_p[k+1], t = p >> 4, f = p & 15;
            xpatch[((k+1) & 1) * 512 + tid] = tile[(t + gr) * TP + f + gc];
        }
        unsigned rw = (k == 0) ? 0u : (s_res[wid >> 2] >> ((wid & 3) * 8));
        #pragma unroll
        for (int j = 0; j < 8; ++j) {
            if ((rw >> j) & 1u) continue;
            int c = wid * 8 + j;
            const float4* Wc = Ws + (size_t)c * 128;
            float4 w0 = Wc[lane], w1 = Wc[lane+32], w2 = Wc[lane+64], w3 = Wc[lane+96];
            float a = 0.f;
            a = fmaf(w0.x, xq0.x, a); a = fmaf(w0.y, xq0.y, a); a = fmaf(w0.z, xq0.z, a); a = fmaf(w0.w, xq0.w, a);
            a = fmaf(w1.x, xq1.x, a); a = fmaf(w1.y, xq1.y, a); a = fmaf(w1.z, xq1.z, a); a = fmaf(w1.w, xq1.w, a);
            a = fmaf(w2.x, xq2.x, a); a = fmaf(w2.y, xq2.y, a); a = fmaf(w2.z, xq2.z, a); a = fmaf(w2.w, xq2.w, a);
            a = fmaf(w3.x, xq3.x, a); a = fmaf(w3.y, xq3.y, a); a = fmaf(w3.z, xq3.z, a); a = fmaf(w3.w, xq3.w, a);
            #pragma unroll
            for (int d = 16; d; d >>= 1) a += __shfl_xor_sync(~0u, a, d);
            if (lane == 0 && a >= THR) {
                atomicOr(&s_pool[c >> 5], 1u << (c & 31));
                atomicOr(&s_res[c >> 5],  1u << (c & 31));
            }
        }
        __syncthreads();
        if ((s_res[0] & s_res[1] & s_res[2] & s_res[3]) == 0xffffffffu) break;
    }

    // ================= rigorous cold path =================
    if ((s_res[0] & s_res[1] & s_res[2] & s_res[3]) != 0xffffffffu) {
        // sumsq rows (lazy)
        if (tid < LPRE) {
            float a2 = 0.f;
            #pragma unroll
            for (int c = 0; c < 16; ++c) { float x = tile[tid*TP + c]; a2 += x*x; }
            Rrow2[tid*RP] = a2;
            for (int f = 1; f < 16; ++f) {
                float xo = tile[tid*TP + f - 1], xn = tile[tid*TP + f + 15];
                a2 += xn*xn - xo*xo;
                Rrow2[tid*RP + f] = a2;
            }
        }
        __syncthreads();
        // column sumsq -> variance array
        if (tid < 400) {
            int f = tid & 15, t0 = (tid >> 4) * 16;
            float a2 = 0.f;
            for (int k = 0; k < 32; ++k) a2 += Rrow2[(t0+k)*RP+f];
            float lsig = 0.f;
            for (int t = t0; t < t0 + 16; ++t) {
                int p = t*16 + f;
                float S = Sarr[p];
                float var = fmaxf(a2 - S*S*(1.0f/512.0f), 0.f);
                Varr[p] = var;
                lsig = fmaxf(lsig, var);
                if (t <= 398) a2 += Rrow2[(t+32)*RP+f] - Rrow2[t*RP+f];
            }
            atomicMax(&s_sig_i, __float_as_int(lsig));
        }
        __syncthreads();

        // per-channel Sw / Bn for unresolved channels
        for (int c = wid; c < NC; c += 16) {
            if ((s_res[c >> 5] >> (c & 31)) & 1u) continue;
            const float4* Wc = Ws + (size_t)c * 128;
            float4 w0 = Wc[lane], w1 = Wc[lane+32], w2 = Wc[lane+64], w3 = Wc[lane+96];
            float ws = (w0.x+w0.y+w0.z+w0.w) + (w1.x+w1.y+w1.z+w1.w)
                     + (w2.x+w2.y+w2.z+w2.w) + (w3.x+w3.y+w3.z+w3.w);
            float wq = (w0.x*w0.x+w0.y*w0.y+w0.z*w0.z+w0.w*w0.w)
                     + (w1.x*w1.x+w1.y*w1.y+w1.z*w1.z+w1.w*w1.w)
                     + (w2.x*w2.x+w2.y*w2.y+w2.z*w2.z+w2.w*w2.w)
                     + (w3.x*w3.x+w3.y*w3.y+w3.z*w3.z+w3.w*w3.w);
            #pragma unroll
            for (int d = 16; d; d >>= 1) {
                ws += __shfl_xor_sync(~0u, ws, d);
                wq += __shfl_xor_sync(~0u, wq, d);
            }
            if (lane == 0) {
                s_cw[c] = ws;
                s_cb[c] = sqrtf(fmaxf(wq - ws*ws*(1.0f/512.0f), 0.f));
            }
        }
        __syncthreads();

        const float Smax   = Sarr[s_p[0]];
        const float sigMax = sqrtf(__int_as_float(s_sig_i));
        if (tid < NC && !((s_res[tid >> 5] >> (tid & 31)) & 1u)) {
            if (s_cw[tid] * Smax * (1.0f/512.0f) + s_cb[tid] * sigMax >= THR - MARGIN)
                s_rem[atomicAdd(&s_rcnt, 1)] = tid;
        }
        __syncthreads();

        float* wbuf = xpatch;                       // 512-float reuse
        const int rbase = (lane >> 4);              // row offset for my taps
        const int cofs  = (lane & 15);              // col offset

        for (int ri = 0; ri < s_rcnt; ++ri) {
            const int cc = s_rem[ri];
            // stage channel W into smem (coalesced)
            if (tid < 128)
                ((float4*)wbuf)[tid] = Ws[(size_t)cc * 128 + tid];
            if (tid == 0) s_cfired = 0;
            __syncthreads();

            const float cw = s_cw[cc], cb2 = s_cb[cc] * s_cb[cc];
            volatile int* cf = &s_cfired;
            int fired = 0;
            for (int p0 = wid * 400; p0 < wid * 400 + 400 && !fired && !*cf; p0 += 32) {
                int p = p0 + lane;
                float S   = Sarr[p];
                float var = Varr[p];
                float base = cw * S * (1.0f/512.0f);
                float d1 = base - (THR + MARGIN);        // fire if d1 >= cb*sn
                float d2 = (THR - MARGIN) - base;        // dead if d2 > cb*sn
                bool fl  = (d1 >= 0.f) && (d1*d1 >= cb2*var);
                bool amb = !fl && ((d2 <= 0.f) || (d2*d2 <= cb2*var));
                if (__ballot_sync(~0u, fl)) fired = 1;
                unsigned am = __ballot_sync(~0u, amb);
                while (am && !fired) {
                    int l0 = __ffs(am) - 1; am &= am - 1;
                    int has2 = (am != 0u);
                    int l1 = has2 ? (__ffs(am) - 1) : l0;
                    if (has2) am &= am - 1;
                    int pa = __shfl_sync(~0u, p, l0);
                    int pb = __shfl_sync(~0u, p, l1);
                    int ta = pa >> 4, fa = pa & 15;
                    int tb = pb >> 4, fb = pb & 15;
                    const float* xa = tile + (ta + rbase) * TP + fa + cofs;
                    const float* xb = tile + (tb + rbase) * TP + fb + cofs;
                    float a0 = 0.f, a1 = 0.f;
                    #pragma unroll
                    for (int i = 0; i < 16; ++i) {
                        float wv = wbuf[lane + 32*i];
                        a0 = fmaf(wv, xa[66*i], a0);     // 2 rows per step: 2*TP = 66
                        a1 = fmaf(wv, xb[66*i], a1);
                    }
                    #pragma unroll
                    for (int d = 16; d; d >>= 1) {
                        a0 += __shfl_xor_sync(~0u, a0, d);
                        a1 += __shfl_xor_sync(~0u, a1, d);
                    }
                    if (a0 >= THR || (has2 && a1 >= THR)) fired = 1;
                }
            }
            if (fired && lane == 0) {
                atomicOr(&s_pool[cc >> 5], 1u << (cc & 31));
                s_cfired = 1;
            }
            __syncthreads();
        }
    }
    __syncthreads();

    if (tid < 4)
        g_poolw[(s * NFW + fwin) * 4 + tid] = s_pool[tid];

    // ---- fused winner reduction (last CTA) ----
    __threadfence();
    __syncthreads();
    if (tid == 0) s_last = (atomicAdd(&g_done, 1u) == gridDim.x - 1u);
    __syncthreads();
    if (!s_last) return;
    __threadfence();

    if (tid == 0) { s_any = 0; s_key0 = -1; s_key1 = -1; }
    __syncthreads();

    int lk0 = -1, lk1 = -1, localany = 0;
    for (int cell = tid; cell < NC * NFW; cell += 512) {
        int cc = cell / NFW, f = cell % NFW;
        int wword = cc >> 5, wbit = cc & 31;
        unsigned mask = 0; int cnt = 0;
        #pragma unroll
        for (int ss = 0; ss < NS; ++ss) {
            int b = (int)((g_poolw[(ss * NFW + f) * 4 + wword] >> wbit) & 1u);
            mask |= (unsigned)b << ss; cnt += b;
        }
        int e = 8 - cnt; e = e < 0 ? 0 : (e > 7 ? 7 : e);
        int val = (int)((mask >> e) & 1u);
        if (cnt > 0 && val > 0) localany = 1;
        int k0 = ((cnt * val)       << 11) | (2047 - cell);
        int k1 = ((cnt * (val + 8)) << 11) | (2047 - cell);
        if (k0 > lk0) lk0 = k0;
        if (k1 > lk1) lk1 = k1;
    }
    #pragma unroll
    for (int d = 16; d; d >>= 1) {
        lk0 = max(lk0, __shfl_xor_sync(~0u, lk0, d));
        lk1 = max(lk1, __shfl_xor_sync(~0u, lk1, d));
        localany |= __shfl_xor_sync(~0u, localany, d);
    }
    if (lane == 0) {
        atomicMax(&s_key0, lk0);
        atomicMax(&s_key1, lk1);
        if (localany) atomicOr(&s_any, 1);
    }
    __syncthreads();

    if (tid == 0) {
        int key = s_any ? s_key1 : s_key0;
        int total = key >> 11, cell = 2047 - (key & 2047);
        out[0] = total ? (cell / NFW) : -1;
        g_done = 0;
    }
}

extern "C" void kernel_launch(void* const* d_in, const int* in_sizes, int n_in,
                              void* d_out, int out_size)
{
    (void)n_in; (void)out_size;
    const float* X = (const float*)d_in[0];
    const float* W = (const float*)d_in[1];
    if (in_sizes[0] == NS * NC * KT * KF) { const float* t = X; X = W; W = t; }

    const size_t smem = (size_t)SMEM_F * sizeof(float);
    cudaFuncSetAttribute(spyke_kernel,
                         cudaFuncAttributeMaxDynamicSharedMemorySize, (int)smem);
    spyke_kernel<<<NS * NFW, 512, smem>>>(X, W, (int*)d_out);
}